// round 2
// baseline (speedup 1.0000x reference)
#include <cuda_runtime.h>
#include <cstdint>

#define T_SEQ 2048
#define BATCH 32
#define DIM   512
#define HID   512
#define G4    2048
#define NJ    (T_SEQ * BATCH)   // 65536
#define HPAD  516               // 512 + 4 pad: conflict-free float4 LDS

// ---------------- static device scratch ----------------
__device__ float    g_xproj[(size_t)G4 * NJ];   // [g][t*32+b]  (512 MB)
__device__ float    g_h[2][BATCH * HID];        // [buf][b*512+k]
__device__ unsigned g_bar;

// =====================================================================
// init: h buffer 0 <- h0, reset barrier counter (fresh every launch)
// =====================================================================
__global__ void init_kernel(const float* __restrict__ h0)
{
    int i = blockIdx.x * blockDim.x + threadIdx.x;
    if (i < BATCH * HID) g_h[0][i] = h0[i];
    if (i == 0) g_bar = 0u;
}

// =====================================================================
// Phase 1: x_proj[g][j] = sum_d W_ih[g][d] * input[b][t][d] + b_ih[g] + b_hh[g]
//   j = t*32 + b.  NT-SGEMM, CTA tile 128(M=g) x 128(N=j), K-chunk 16.
//   grid = (NJ/128 = 512, G4/128 = 16), 256 threads.
// =====================================================================
#define KC 16

__global__ __launch_bounds__(256) void xproj_kernel(
    const float* __restrict__ input,
    const float* __restrict__ W_ih,
    const float* __restrict__ b_ih,
    const float* __restrict__ b_hh)
{
    __shared__ float As[KC][128];   // A^T tile: [k][m]
    __shared__ float Bs[KC][128];   // B^T tile: [k][j]

    const int tid = threadIdx.x;
    const int gm0 = blockIdx.y * 128;
    const int jn0 = blockIdx.x * 128;
    const int tx  = tid & 15;       // n-group
    const int ty  = tid >> 4;       // m-group

    float acc[8][8];
    #pragma unroll
    for (int i = 0; i < 8; ++i)
        #pragma unroll
        for (int j = 0; j < 8; ++j) acc[i][j] = 0.f;

    for (int kc = 0; kc < DIM; kc += KC) {
        // stage A tile (128 m x 16 k): 512 float4, 2 per thread
        #pragma unroll
        for (int i = 0; i < 2; ++i) {
            int idx = tid + i * 256;
            int m = idx >> 2, kq = (idx & 3) * 4;
            float4 v = *reinterpret_cast<const float4*>(
                W_ih + (size_t)(gm0 + m) * DIM + kc + kq);
            As[kq + 0][m] = v.x; As[kq + 1][m] = v.y;
            As[kq + 2][m] = v.z; As[kq + 3][m] = v.w;
        }
        // stage B tile (128 j x 16 k)
        #pragma unroll
        for (int i = 0; i < 2; ++i) {
            int idx = tid + i * 256;
            int j = idx >> 2, kq = (idx & 3) * 4;
            int b = j & 31;                 // jn0 is a multiple of 128
            int t = (jn0 + j) >> 5;
            float4 v = *reinterpret_cast<const float4*>(
                input + ((size_t)b * T_SEQ + t) * DIM + kc + kq);
            Bs[kq + 0][j] = v.x; Bs[kq + 1][j] = v.y;
            Bs[kq + 2][j] = v.z; Bs[kq + 3][j] = v.w;
        }
        __syncthreads();

        #pragma unroll
        for (int k = 0; k < KC; ++k) {
            float a[8], bf[8];
            *reinterpret_cast<float4*>(a)      = *reinterpret_cast<const float4*>(&As[k][ty * 8]);
            *reinterpret_cast<float4*>(a + 4)  = *reinterpret_cast<const float4*>(&As[k][ty * 8 + 4]);
            *reinterpret_cast<float4*>(bf)     = *reinterpret_cast<const float4*>(&Bs[k][tx * 8]);
            *reinterpret_cast<float4*>(bf + 4) = *reinterpret_cast<const float4*>(&Bs[k][tx * 8 + 4]);
            #pragma unroll
            for (int i = 0; i < 8; ++i)
                #pragma unroll
                for (int j = 0; j < 8; ++j)
                    acc[i][j] += a[i] * bf[j];
        }
        __syncthreads();
    }

    // epilogue: add bias, store [g][j] (coalesced over j)
    #pragma unroll
    for (int i = 0; i < 8; ++i) {
        int g = gm0 + ty * 8 + i;
        float bias = __ldg(b_ih + g) + __ldg(b_hh + g);
        float* cp = g_xproj + (size_t)g * NJ + jn0 + tx * 8;
        float4 s0 = make_float4(acc[i][0] + bias, acc[i][1] + bias,
                                acc[i][2] + bias, acc[i][3] + bias);
        float4 s1 = make_float4(acc[i][4] + bias, acc[i][5] + bias,
                                acc[i][6] + bias, acc[i][7] + bias);
        *reinterpret_cast<float4*>(cp)     = s0;
        *reinterpret_cast<float4*>(cp + 4) = s1;
    }
}

// =====================================================================
// Phase 2: persistent recurrent kernel.
//   128 CTAs x 256 threads. CTA c owns hidden units [4c, 4c+4) -> 16 gate
//   rows {q*512 + 4c+uu}. W slice resident in shared; h staged per step.
//   Grid barrier: threadfence + atomic counter (monotone target).
// =====================================================================
#define NCTA 128
#define SMEM_FLOATS (16 * HPAD + 32 * HPAD + 16 * 32)
#define SMEM_BYTES  (SMEM_FLOATS * sizeof(float))

__global__ __launch_bounds__(256) void lstm_kernel(
    const float* __restrict__ W_hh,
    const float* __restrict__ c0,
    float* __restrict__ out)
{
    extern __shared__ float sm[];
    float* W_s    = sm;                        // [16][HPAD]
    float* h_s    = sm + 16 * HPAD;            // [32][HPAD]
    float* gate_s = sm + 16 * HPAD + 32 * HPAD; // [16][32]

    const int tid = threadIdx.x;
    const int cta = blockIdx.x;

    // ---- load W slice once: local row r = uu*4 + q, global row q*512 + 4*cta+uu
    for (int idx = tid; idx < 16 * 128; idx += 256) {
        int r = idx >> 7, kq = (idx & 127) * 4;
        int grow = (r & 3) * HID + cta * 4 + (r >> 2);
        float4 v = *reinterpret_cast<const float4*>(W_hh + (size_t)grow * HID + kq);
        *reinterpret_cast<float4*>(W_s + r * HPAD + kq) = v;
    }

    // roles
    const int slot = tid >> 5;        // dot threads (tid<128): warp id 0..3
    const int b    = tid & 31;        //   batch lane
    const int uu   = tid >> 5;        // cell threads (tid<128): unit 0..3
    const int unit = cta * 4 + uu;

    float c_state = 0.f;
    if (tid < 128) c_state = __ldg(c0 + b * HID + unit);

    unsigned target = NCTA;

    for (int t = 0; t < T_SEQ; ++t) {
        const int cur = t & 1;

        // prefetch x_proj for this step's rows (dot threads)
        float xv0 = 0.f, xv1 = 0.f, xv2 = 0.f, xv3 = 0.f;
        if (tid < 128) {
            const size_t jo = (size_t)t * 32 + b;
            int r0 = slot * 4;
            int gr0 = ((r0 + 0) & 3) * HID + cta * 4 + ((r0 + 0) >> 2);
            int gr1 = ((r0 + 1) & 3) * HID + cta * 4 + ((r0 + 1) >> 2);
            int gr2 = ((r0 + 2) & 3) * HID + cta * 4 + ((r0 + 2) >> 2);
            int gr3 = ((r0 + 3) & 3) * HID + cta * 4 + ((r0 + 3) >> 2);
            xv0 = __ldg(&g_xproj[(size_t)gr0 * NJ + jo]);
            xv1 = __ldg(&g_xproj[(size_t)gr1 * NJ + jo]);
            xv2 = __ldg(&g_xproj[(size_t)gr2 * NJ + jo]);
            xv3 = __ldg(&g_xproj[(size_t)gr3 * NJ + jo]);
        }

        // stage h (64 KB) from L2 (skip L1: other SMs wrote it last step)
        for (int idx = tid; idx < 32 * 128; idx += 256) {
            int bb = idx >> 7, kq = (idx & 127) * 4;
            float4 v = __ldcg(reinterpret_cast<const float4*>(g_h[cur] + bb * HID + kq));
            *reinterpret_cast<float4*>(h_s + bb * HPAD + kq) = v;
        }
        __syncthreads();

        // ---- dot: 4 rows x 1 batch per thread, float4 over k
        if (tid < 128) {
            float a0 = 0.f, a1 = 0.f, a2 = 0.f, a3 = 0.f;
            const float* hp = h_s + b * HPAD;
            const float* w0 = W_s + (slot * 4 + 0) * HPAD;
            const float* w1 = W_s + (slot * 4 + 1) * HPAD;
            const float* w2 = W_s + (slot * 4 + 2) * HPAD;
            const float* w3 = W_s + (slot * 4 + 3) * HPAD;
            #pragma unroll 4
            for (int k = 0; k < HID; k += 4) {
                float4 hv = *reinterpret_cast<const float4*>(hp + k);
                float4 v0 = *reinterpret_cast<const float4*>(w0 + k);
                float4 v1 = *reinterpret_cast<const float4*>(w1 + k);
                float4 v2 = *reinterpret_cast<const float4*>(w2 + k);
                float4 v3 = *reinterpret_cast<const float4*>(w3 + k);
                a0 += v0.x * hv.x + v0.y * hv.y + v0.z * hv.z + v0.w * hv.w;
                a1 += v1.x * hv.x + v1.y * hv.y + v1.z * hv.z + v1.w * hv.w;
                a2 += v2.x * hv.x + v2.y * hv.y + v2.z * hv.z + v2.w * hv.w;
                a3 += v3.x * hv.x + v3.y * hv.y + v3.z * hv.z + v3.w * hv.w;
            }
            gate_s[(slot * 4 + 0) * 32 + b] = a0 + xv0;
            gate_s[(slot * 4 + 1) * 32 + b] = a1 + xv1;
            gate_s[(slot * 4 + 2) * 32 + b] = a2 + xv2;
            gate_s[(slot * 4 + 3) * 32 + b] = a3 + xv3;
        }
        __syncthreads();

        // ---- cell update (tid<128: unit uu, batch b)
        if (tid < 128) {
            float gi = gate_s[(uu * 4 + 0) * 32 + b];
            float gf = gate_s[(uu * 4 + 1) * 32 + b];
            float gg = gate_s[(uu * 4 + 2) * 32 + b];
            float go = gate_s[(uu * 4 + 3) * 32 + b];
            float i_ = 1.f / (1.f + expf(-gi));
            float f_ = 1.f / (1.f + expf(-gf));
            float g_ = tanhf(gg);
            float o_ = 1.f / (1.f + expf(-go));
            c_state = f_ * c_state + i_ * g_;
            float h_new = o_ * tanhf(c_state);
            g_h[cur ^ 1][b * HID + unit] = h_new;
            if (t == T_SEQ - 1) {
                out[b * HID + unit] = h_new;                 // h
                out[BATCH * HID + b * HID + unit] = c_state; // c
            }
            __threadfence();   // make h store visible before barrier arrive
        }

        // ---- grid barrier
        __syncthreads();
        if (tid == 0) {
            __threadfence();
            unsigned v = atomicAdd(&g_bar, 1u) + 1u;
            if (v < target) {
                while (atomicAdd(&g_bar, 0u) < target) { __nanosleep(40); }
            }
        }
        __syncthreads();
        target += NCTA;
    }
}

// =====================================================================
// launch
// =====================================================================
extern "C" void kernel_launch(void* const* d_in, const int* in_sizes, int n_in,
                              void* d_out, int out_size)
{
    const float* input = (const float*)d_in[0];
    const float* h0    = (const float*)d_in[1];
    const float* c0    = (const float*)d_in[2];
    const float* W_ih  = (const float*)d_in[3];
    const float* W_hh  = (const float*)d_in[4];
    const float* b_ih  = (const float*)d_in[5];
    const float* b_hh  = (const float*)d_in[6];
    float* out = (float*)d_out;

    cudaFuncSetAttribute(lstm_kernel,
                         cudaFuncAttributeMaxDynamicSharedMemorySize,
                         (int)SMEM_BYTES);

    init_kernel<<<64, 256>>>(h0);
    xproj_kernel<<<dim3(NJ / 128, G4 / 128), 256>>>(input, W_ih, b_ih, b_hh);
    lstm_kernel<<<NCTA, 256, SMEM_BYTES>>>(W_hh, c0, out);
}

// round 3
// speedup vs baseline: 1.6110x; 1.6110x over previous
#include <cuda_runtime.h>
#include <cstdint>

#define T_SEQ 2048
#define BATCH 32
#define DIM   512
#define HID   512
#define G4    2048
#define NJ    (T_SEQ * BATCH)   // 65536

// ---------------- static device scratch ----------------
__device__ float    g_xproj[(size_t)G4 * NJ];   // [g][t*32+b]  (512 MB)
__device__ float    g_h[2][HID * BATCH];        // [buf][k*32+b]  (k=unit)
__device__ unsigned g_bar;

// ---------------- helpers ----------------
__device__ __forceinline__ float tf32_rna(float f) {
    float r;
    asm("cvt.rna.tf32.f32 %0, %1;" : "=f"(r) : "f"(f));
    return r;
}

__device__ __forceinline__ void mma_tf32(float c[4], const unsigned a[4],
                                         unsigned b0, unsigned b1) {
    asm volatile(
        "mma.sync.aligned.m16n8k8.row.col.f32.tf32.tf32.f32 "
        "{%0,%1,%2,%3}, {%4,%5,%6,%7}, {%8,%9}, {%0,%1,%2,%3};\n"
        : "+f"(c[0]), "+f"(c[1]), "+f"(c[2]), "+f"(c[3])
        : "r"(a[0]), "r"(a[1]), "r"(a[2]), "r"(a[3]), "r"(b0), "r"(b1));
}

// =====================================================================
// init: g_h[0][k*32+b] = h0[b*512+k]  (transpose), reset barrier
// =====================================================================
__global__ void init_kernel(const float* __restrict__ h0)
{
    int i = blockIdx.x * blockDim.x + threadIdx.x;
    if (i < BATCH * HID) {
        int b = i >> 9, k = i & 511;       // read h0 coalesced
        g_h[0][k * 32 + b] = h0[i];
    }
    if (i == 0) g_bar = 0u;
}

// =====================================================================
// Phase 1: x_proj  (fp32 NT-SGEMM, unchanged from R2 — passing)
// =====================================================================
#define KC 16

__global__ __launch_bounds__(256) void xproj_kernel(
    const float* __restrict__ input,
    const float* __restrict__ W_ih,
    const float* __restrict__ b_ih,
    const float* __restrict__ b_hh)
{
    __shared__ float As[KC][128];
    __shared__ float Bs[KC][128];

    const int tid = threadIdx.x;
    const int gm0 = blockIdx.y * 128;
    const int jn0 = blockIdx.x * 128;
    const int tx  = tid & 15;
    const int ty  = tid >> 4;

    float acc[8][8];
    #pragma unroll
    for (int i = 0; i < 8; ++i)
        #pragma unroll
        for (int j = 0; j < 8; ++j) acc[i][j] = 0.f;

    for (int kc = 0; kc < DIM; kc += KC) {
        #pragma unroll
        for (int i = 0; i < 2; ++i) {
            int idx = tid + i * 256;
            int m = idx >> 2, kq = (idx & 3) * 4;
            float4 v = *reinterpret_cast<const float4*>(
                W_ih + (size_t)(gm0 + m) * DIM + kc + kq);
            As[kq + 0][m] = v.x; As[kq + 1][m] = v.y;
            As[kq + 2][m] = v.z; As[kq + 3][m] = v.w;
        }
        #pragma unroll
        for (int i = 0; i < 2; ++i) {
            int idx = tid + i * 256;
            int j = idx >> 2, kq = (idx & 3) * 4;
            int b = j & 31;
            int t = (jn0 + j) >> 5;
            float4 v = *reinterpret_cast<const float4*>(
                input + ((size_t)b * T_SEQ + t) * DIM + kc + kq);
            Bs[kq + 0][j] = v.x; Bs[kq + 1][j] = v.y;
            Bs[kq + 2][j] = v.z; Bs[kq + 3][j] = v.w;
        }
        __syncthreads();

        #pragma unroll
        for (int k = 0; k < KC; ++k) {
            float a[8], bf[8];
            *reinterpret_cast<float4*>(a)      = *reinterpret_cast<const float4*>(&As[k][ty * 8]);
            *reinterpret_cast<float4*>(a + 4)  = *reinterpret_cast<const float4*>(&As[k][ty * 8 + 4]);
            *reinterpret_cast<float4*>(bf)     = *reinterpret_cast<const float4*>(&Bs[k][tx * 8]);
            *reinterpret_cast<float4*>(bf + 4) = *reinterpret_cast<const float4*>(&Bs[k][tx * 8 + 4]);
            #pragma unroll
            for (int i = 0; i < 8; ++i)
                #pragma unroll
                for (int j = 0; j < 8; ++j)
                    acc[i][j] += a[i] * bf[j];
        }
        __syncthreads();
    }

    #pragma unroll
    for (int i = 0; i < 8; ++i) {
        int g = gm0 + ty * 8 + i;
        float bias = __ldg(b_ih + g) + __ldg(b_hh + g);
        float* cp = g_xproj + (size_t)g * NJ + jn0 + tx * 8;
        *reinterpret_cast<float4*>(cp) =
            make_float4(acc[i][0] + bias, acc[i][1] + bias,
                        acc[i][2] + bias, acc[i][3] + bias);
        *reinterpret_cast<float4*>(cp + 4) =
            make_float4(acc[i][4] + bias, acc[i][5] + bias,
                        acc[i][6] + bias, acc[i][7] + bias);
    }
}

// =====================================================================
// Phase 2: persistent recurrent kernel, 3xTF32 tensor-core dots.
//   128 CTAs x 256 threads (8 warps).  CTA owns 4 hidden units ->
//   local gate rows r=0..15, r=(uu<<2)|q, global row q*512 + cta*4 + uu.
//   Warp w handles k in [w*64,(w+1)*64): W frags (hi+lo) in registers.
//   h staged per step [k][b] fp32 -> split to tf32 hi/lo planes, stride 40.
// =====================================================================
#define NCTA   128
#define HS     40                              // smem stride (floats) for h planes
#define H_HI_F 0
#define H_LO_F (HID * HS)                      // 20480
#define PART_F (2 * HID * HS)                  // 40960
#define PSTRIDE 33
#define SMEM_FLOATS (2 * HID * HS + 8 * 16 * PSTRIDE)
#define SMEM_BYTES  (SMEM_FLOATS * sizeof(float))

__global__ __launch_bounds__(256) void lstm_kernel(
    const float* __restrict__ W_hh,
    const float* __restrict__ c0,
    float* __restrict__ out)
{
    extern __shared__ float sm[];
    float* h_hi = sm + H_HI_F;
    float* h_lo = sm + H_LO_F;
    float* part = sm + PART_F;     // [w][r][b] stride PSTRIDE

    const int tid  = threadIdx.x;
    const int cta  = blockIdx.x;
    const int w    = tid >> 5;
    const int lane = tid & 31;
    const int gq   = lane >> 2;    // mma groupID (0..7)
    const int tg   = lane & 3;     // mma threadID_in_group (0..3)

    // ---- load W_hh frags into registers (hi/lo), once ----
    unsigned Ahi[8][4], Alo[8][4];
    #pragma unroll
    for (int kt = 0; kt < 8; ++kt) {
        #pragma unroll
        for (int i = 0; i < 4; ++i) {
            int ra = gq + (i & 1) * 8;            // local row
            int ca = tg + (i >> 1) * 4;           // col within k-tile
            int kg = w * 64 + kt * 8 + ca;
            int G  = (ra & 3) * HID + cta * 4 + (ra >> 2);
            float wv = __ldg(W_hh + (size_t)G * HID + kg);
            float hi = tf32_rna(wv);
            Ahi[kt][i] = __float_as_uint(hi);
            Alo[kt][i] = __float_as_uint(tf32_rna(wv - hi));
        }
    }

    // cell-thread identity (tid < 128)
    const int uu   = tid >> 5;     // 0..3 (valid when tid<128)
    const int b    = tid & 31;
    const int unit = cta * 4 + uu;

    float c_state = 0.f;
    if (tid < 128) c_state = __ldg(c0 + b * HID + unit);

    unsigned target = NCTA;

    for (int t = 0; t < T_SEQ; ++t) {
        const int cur = t & 1;

        // ---- prefetch x_proj rows for this step (cell threads) ----
        float xp[4] = {0.f, 0.f, 0.f, 0.f};
        if (tid < 128) {
            #pragma unroll
            for (int q = 0; q < 4; ++q) {
                int G = q * HID + cta * 4 + uu;
                xp[q] = __ldg(&g_xproj[(size_t)G * NJ + (size_t)t * 32 + b]);
            }
        }

        // ---- stage h from L2 and split to tf32 hi/lo planes ----
        {
            const float4* src = reinterpret_cast<const float4*>(g_h[cur]);
            #pragma unroll
            for (int i = 0; i < 16; ++i) {
                int lin = tid + i * 256;          // 0..4095 float4s
                int k = lin >> 3, b4 = (lin & 7) * 4;
                float4 v = __ldcg(src + lin);
                float4 hi, lo;
                hi.x = tf32_rna(v.x); lo.x = tf32_rna(v.x - hi.x);
                hi.y = tf32_rna(v.y); lo.y = tf32_rna(v.y - hi.y);
                hi.z = tf32_rna(v.z); lo.z = tf32_rna(v.z - hi.z);
                hi.w = tf32_rna(v.w); lo.w = tf32_rna(v.w - hi.w);
                *reinterpret_cast<float4*>(h_hi + k * HS + b4) = hi;
                *reinterpret_cast<float4*>(h_lo + k * HS + b4) = lo;
            }
        }
        __syncthreads();

        // ---- tensor-core dots: warp w covers k in [w*64,(w+1)*64) ----
        float acc[4][4];
        #pragma unroll
        for (int n = 0; n < 4; ++n)
            #pragma unroll
            for (int j = 0; j < 4; ++j) acc[n][j] = 0.f;

        #pragma unroll
        for (int kt = 0; kt < 8; ++kt) {
            const float* Hh = h_hi + (w * 64 + kt * 8) * HS;
            const float* Hl = h_lo + (w * 64 + kt * 8) * HS;
            #pragma unroll
            for (int n = 0; n < 4; ++n) {
                int col = n * 8 + gq;
                unsigned bh0 = __float_as_uint(Hh[tg * HS + col]);
                unsigned bh1 = __float_as_uint(Hh[(tg + 4) * HS + col]);
                unsigned bl0 = __float_as_uint(Hl[tg * HS + col]);
                unsigned bl1 = __float_as_uint(Hl[(tg + 4) * HS + col]);
                mma_tf32(acc[n], Ahi[kt], bh0, bh1);
                mma_tf32(acc[n], Ahi[kt], bl0, bl1);
                mma_tf32(acc[n], Alo[kt], bh0, bh1);
            }
        }

        // ---- write partial gate tiles ----
        {
            float* p = part + w * (16 * PSTRIDE);
            #pragma unroll
            for (int n = 0; n < 4; ++n) {
                int c0i = n * 8 + 2 * tg;
                p[gq * PSTRIDE + c0i]           = acc[n][0];
                p[gq * PSTRIDE + c0i + 1]       = acc[n][1];
                p[(gq + 8) * PSTRIDE + c0i]     = acc[n][2];
                p[(gq + 8) * PSTRIDE + c0i + 1] = acc[n][3];
            }
        }
        __syncthreads();

        // ---- reduce partials + cell update (cell threads) ----
        if (tid < 128) {
            float gate[4];
            #pragma unroll
            for (int q = 0; q < 4; ++q) {
                int r = uu * 4 + q;
                float s = xp[q];
                #pragma unroll
                for (int ww = 0; ww < 8; ++ww)
                    s += part[ww * (16 * PSTRIDE) + r * PSTRIDE + b];
                gate[q] = s;
            }
            float i_ = 1.f / (1.f + expf(-gate[0]));
            float f_ = 1.f / (1.f + expf(-gate[1]));
            float g_ = tanhf(gate[2]);
            float o_ = 1.f / (1.f + expf(-gate[3]));
            c_state = f_ * c_state + i_ * g_;
            float h_new = o_ * tanhf(c_state);
            g_h[cur ^ 1][unit * 32 + b] = h_new;
            if (t == T_SEQ - 1) {
                out[b * HID + unit] = h_new;                 // h
                out[BATCH * HID + b * HID + unit] = c_state; // c
            }
            __threadfence();
        }

        // ---- grid barrier ----
        __syncthreads();
        if (tid == 0) {
            __threadfence();
            unsigned v = atomicAdd(&g_bar, 1u) + 1u;
            if (v < target) {
                while (atomicAdd(&g_bar, 0u) < target) { __nanosleep(64); }
            }
        }
        __syncthreads();
        target += NCTA;
    }
}

// =====================================================================
// launch
// =====================================================================
extern "C" void kernel_launch(void* const* d_in, const int* in_sizes, int n_in,
                              void* d_out, int out_size)
{
    const float* input = (const float*)d_in[0];
    const float* h0    = (const float*)d_in[1];
    const float* c0    = (const float*)d_in[2];
    const float* W_ih  = (const float*)d_in[3];
    const float* W_hh  = (const float*)d_in[4];
    const float* b_ih  = (const float*)d_in[5];
    const float* b_hh  = (const float*)d_in[6];
    float* out = (float*)d_out;

    cudaFuncSetAttribute(lstm_kernel,
                         cudaFuncAttributeMaxDynamicSharedMemorySize,
                         (int)SMEM_BYTES);

    init_kernel<<<64, 256>>>(h0);
    xproj_kernel<<<dim3(NJ / 128, G4 / 128), 256>>>(input, W_ih, b_ih, b_hh);
    lstm_kernel<<<NCTA, 256, SMEM_BYTES>>>(W_hh, c0, out);
}

// round 5
// speedup vs baseline: 2.3200x; 1.4401x over previous
#include <cuda_runtime.h>
#include <cuda_bf16.h>
#include <cstdint>

#define T_SEQ 2048
#define BATCH 32
#define DIM   512
#define HID   512
#define G4    2048
#define NJ    (T_SEQ * BATCH)   // 65536
#define NCTA  128

// ---------------- static device scratch ----------------
__device__ float    g_xproj[(size_t)G4 * NJ];                  // [g][t*32+b] fp32 (512MB)
__device__ unsigned g_xhi[(size_t)BATCH * T_SEQ * DIM / 2];    // bf16 pairs along d
__device__ unsigned g_xlo[(size_t)BATCH * T_SEQ * DIM / 2];
__device__ unsigned g_whi[(size_t)G4 * DIM / 2];
__device__ unsigned g_wlo[(size_t)G4 * DIM / 2];
__device__ unsigned g_hhi[2][(HID / 2) * BATCH];               // word idx = k2*32+b
__device__ unsigned g_hlo[2][(HID / 2) * BATCH];
__device__ unsigned g_bar;

// ---------------- helpers ----------------
__device__ __forceinline__ void mma_bf16(float c[4], const unsigned a[4],
                                         unsigned b0, unsigned b1) {
    asm volatile(
        "mma.sync.aligned.m16n8k16.row.col.f32.bf16.bf16.f32 "
        "{%0,%1,%2,%3}, {%4,%5,%6,%7}, {%8,%9}, {%0,%1,%2,%3};\n"
        : "+f"(c[0]), "+f"(c[1]), "+f"(c[2]), "+f"(c[3])
        : "r"(a[0]), "r"(a[1]), "r"(a[2]), "r"(a[3]), "r"(b0), "r"(b1));
}

__device__ __forceinline__ unsigned split_pack(float v0, float v1, unsigned& lo_bits) {
    __nv_bfloat162 hi = __floats2bfloat162_rn(v0, v1);
    __nv_bfloat162 lo = __floats2bfloat162_rn(v0 - __bfloat162float(hi.x),
                                              v1 - __bfloat162float(hi.y));
    lo_bits = *reinterpret_cast<unsigned*>(&lo);
    return *reinterpret_cast<unsigned*>(&hi);
}

__device__ __forceinline__ float sigf(float x) {
    return __fdividef(1.f, 1.f + __expf(-x));
}
__device__ __forceinline__ float tanh_fast(float x) {
    return __fdividef(2.f, 1.f + __expf(-2.f * x)) - 1.f;
}

// =====================================================================
// convert: split input & W_ih into bf16 hi/lo packed-pair planes
// =====================================================================
__global__ void convert_kernel(const float* __restrict__ x,
                               const float* __restrict__ wih)
{
    const size_t n_x = (size_t)BATCH * T_SEQ * DIM / 2;   // 16777216 words
    const size_t n_w = (size_t)G4 * DIM / 2;              //   524288 words
    const size_t stride = (size_t)gridDim.x * blockDim.x;
    for (size_t i = blockIdx.x * (size_t)blockDim.x + threadIdx.x;
         i < n_x; i += stride) {
        float2 v = reinterpret_cast<const float2*>(x)[i];
        unsigned lo;
        unsigned hi = split_pack(v.x, v.y, lo);
        g_xhi[i] = hi; g_xlo[i] = lo;
    }
    for (size_t i = blockIdx.x * (size_t)blockDim.x + threadIdx.x;
         i < n_w; i += stride) {
        float2 v = reinterpret_cast<const float2*>(wih)[i];
        unsigned lo;
        unsigned hi = split_pack(v.x, v.y, lo);
        g_whi[i] = hi; g_wlo[i] = lo;
    }
}

// =====================================================================
// init: h planes (buffer 0) from h0, reset barrier
// =====================================================================
__global__ void init_kernel(const float* __restrict__ h0)
{
    int i = blockIdx.x * blockDim.x + threadIdx.x;   // word index
    if (i < (HID / 2) * BATCH) {
        int k2 = i >> 5, b = i & 31;
        float v0 = h0[b * HID + 2 * k2];
        float v1 = h0[b * HID + 2 * k2 + 1];
        unsigned lo;
        unsigned hi = split_pack(v0, v1, lo);
        g_hhi[0][i] = hi; g_hlo[0][i] = lo;
    }
    if (i == 0) g_bar = 0u;
}

// =====================================================================
// Phase 1: x_proj via bf16x3 mma. CTA tile 128(g) x 128(j), K-chunk 32.
// grid = (16 g-blocks, 512 j-blocks), 256 threads (8 warps: 2m x 4n).
// smem rows stride SA=20 words -> frag LDS bank pattern (gq*20+tg) all distinct.
// =====================================================================
#define SA 20

__global__ __launch_bounds__(256) void xproj_kernel(
    const float* __restrict__ b_ih,
    const float* __restrict__ b_hh)
{
    __shared__ unsigned sm[4 * 128 * SA];   // Ahi | Alo | Bhi | Blo
    unsigned* Ahs = sm;
    unsigned* Als = sm + 128 * SA;
    unsigned* Bhs = sm + 2 * 128 * SA;
    unsigned* Bls = sm + 3 * 128 * SA;

    const int tid = threadIdx.x;
    const int w = tid >> 5, lane = tid & 31;
    const int gq = lane >> 2, tg = lane & 3;
    const int gm0 = blockIdx.x * 128;
    const int jn0 = blockIdx.y * 128;
    const int wm = (w >> 2) * 64;   // warp m offset: 0 / 64
    const int wn = (w & 3) * 32;    // warp n offset: 0..96

    float acc[4][4][4];
    #pragma unroll
    for (int m = 0; m < 4; ++m)
        #pragma unroll
        for (int n = 0; n < 4; ++n)
            #pragma unroll
            for (int r = 0; r < 4; ++r) acc[m][n][r] = 0.f;

    for (int kc2 = 0; kc2 < DIM / 2; kc2 += 16) {   // 16 chunks of 32 k
        // ---- stage A planes (128 rows x 16 words) ----
        #pragma unroll
        for (int i = 0; i < 2; ++i) {
            int idx = tid + i * 256;                 // 0..511
            int m = idx >> 2, q4 = (idx & 3) * 4;
            size_t gw = (size_t)(gm0 + m) * (DIM / 2) + kc2 + q4;
            *reinterpret_cast<uint4*>(&Ahs[m * SA + q4]) =
                *reinterpret_cast<const uint4*>(&g_whi[gw]);
            *reinterpret_cast<uint4*>(&Als[m * SA + q4]) =
                *reinterpret_cast<const uint4*>(&g_wlo[gw]);
        }
        // ---- stage B planes (128 j-rows x 16 words) ----
        #pragma unroll
        for (int i = 0; i < 2; ++i) {
            int idx = tid + i * 256;
            int j = idx >> 2, q4 = (idx & 3) * 4;
            int b = j & 31;                          // jn0 multiple of 128
            int t = (jn0 + j) >> 5;
            size_t gw = ((size_t)b * T_SEQ + t) * (DIM / 2) + kc2 + q4;
            *reinterpret_cast<uint4*>(&Bhs[j * SA + q4]) =
                *reinterpret_cast<const uint4*>(&g_xhi[gw]);
            *reinterpret_cast<uint4*>(&Bls[j * SA + q4]) =
                *reinterpret_cast<const uint4*>(&g_xlo[gw]);
        }
        __syncthreads();

        #pragma unroll
        for (int kt = 0; kt < 2; ++kt) {
            const int k2o = kt * 8;
            unsigned bh[4][2], bl[4][2];
            #pragma unroll
            for (int n = 0; n < 4; ++n) {
                int j = wn + n * 8 + gq;
                bh[n][0] = Bhs[j * SA + k2o + tg];
                bh[n][1] = Bhs[j * SA + k2o + tg + 4];
                bl[n][0] = Bls[j * SA + k2o + tg];
                bl[n][1] = Bls[j * SA + k2o + tg + 4];
            }
            #pragma unroll
            for (int m = 0; m < 4; ++m) {
                int r0 = wm + m * 16 + gq;
                unsigned ah[4], al[4];
                ah[0] = Ahs[r0 * SA + k2o + tg];
                ah[1] = Ahs[(r0 + 8) * SA + k2o + tg];
                ah[2] = Ahs[r0 * SA + k2o + tg + 4];
                ah[3] = Ahs[(r0 + 8) * SA + k2o + tg + 4];
                al[0] = Als[r0 * SA + k2o + tg];
                al[1] = Als[(r0 + 8) * SA + k2o + tg];
                al[2] = Als[r0 * SA + k2o + tg + 4];
                al[3] = Als[(r0 + 8) * SA + k2o + tg + 4];
                #pragma unroll
                for (int n = 0; n < 4; ++n) {
                    mma_bf16(acc[m][n], ah, bh[n][0], bh[n][1]);
                    mma_bf16(acc[m][n], ah, bl[n][0], bl[n][1]);
                    mma_bf16(acc[m][n], al, bh[n][0], bh[n][1]);
                }
            }
        }
        __syncthreads();
    }

    // ---- epilogue: bias + fp32 store (float2, 32B-sector efficient) ----
    #pragma unroll
    for (int m = 0; m < 4; ++m) {
        int g0 = gm0 + wm + m * 16 + gq;
        float bi0 = __ldg(b_ih + g0) + __ldg(b_hh + g0);
        float bi1 = __ldg(b_ih + g0 + 8) + __ldg(b_hh + g0 + 8);
        #pragma unroll
        for (int n = 0; n < 4; ++n) {
            int j0 = jn0 + wn + n * 8 + tg * 2;
            float2 v0 = make_float2(acc[m][n][0] + bi0, acc[m][n][1] + bi0);
            float2 v1 = make_float2(acc[m][n][2] + bi1, acc[m][n][3] + bi1);
            *reinterpret_cast<float2*>(g_xproj + (size_t)g0 * NJ + j0) = v0;
            *reinterpret_cast<float2*>(g_xproj + (size_t)(g0 + 8) * NJ + j0) = v1;
        }
    }
}

// =====================================================================
// Phase 2: persistent recurrent kernel, bf16x3.
//   128 CTAs x 256 threads. CTA owns 4 units -> 16 gate rows (M=16).
//   Warp w: k in [w*64,(w+1)*64), W frags in regs (hi+lo, 32 regs).
//   h planes pre-packed (k-pair words) -> staging is a pure copy.
//   smem h stride 40 words: frag banks = tg*8+gq, conflict-free.
// =====================================================================
#define HSW 40
#define SMEM_WORDS (2 * 256 * HSW + 8 * 16 * 33)
#define SMEM_BYTES (SMEM_WORDS * 4)

__global__ __launch_bounds__(256) void lstm_kernel(
    const float* __restrict__ W_hh,
    const float* __restrict__ c0,
    float* __restrict__ out)
{
    extern __shared__ unsigned smw[];
    unsigned* s_hhi = smw;                    // [256][HSW]
    unsigned* s_hlo = smw + 256 * HSW;
    float*    part  = reinterpret_cast<float*>(smw + 2 * 256 * HSW); // [8][16][33]

    const int tid = threadIdx.x;
    const int cta = blockIdx.x;
    const int w = tid >> 5, lane = tid & 31;
    const int gq = lane >> 2, tg = lane & 3;

    // ---- W_hh frags into registers (hi/lo), once ----
    unsigned Ahi[4][4], Alo[4][4];
    #pragma unroll
    for (int kt = 0; kt < 4; ++kt) {
        #pragma unroll
        for (int i = 0; i < 4; ++i) {
            int r   = gq + ((i & 1) << 3);        // local row 0..15 (r = uu*4+q)
            int k2l = tg + ((i >> 1) << 2);       // 0..7
            int kg  = w * 64 + kt * 16 + k2l * 2;
            int G   = (r & 3) * HID + cta * 4 + (r >> 2);
            float w0 = __ldg(W_hh + (size_t)G * HID + kg);
            float w1 = __ldg(W_hh + (size_t)G * HID + kg + 1);
            unsigned lo;
            Ahi[kt][i] = split_pack(w0, w1, lo);
            Alo[kt][i] = lo;
        }
    }

    // cell threads: tid<64, pair pr = tid>>5 (units 2pr, 2pr+1), batch b
    const int pr = tid >> 5;
    const int b  = lane;
    float cst[2] = {0.f, 0.f};
    if (tid < 64) {
        cst[0] = __ldg(c0 + b * HID + cta * 4 + 2 * pr);
        cst[1] = __ldg(c0 + b * HID + cta * 4 + 2 * pr + 1);
    }

    unsigned target = NCTA;

    for (int t = 0; t < T_SEQ; ++t) {
        const int cur = t & 1;

        // ---- xp prefetch (cell threads): 8 gates ----
        float xp[8];
        if (tid < 64) {
            #pragma unroll
            for (int j2 = 0; j2 < 2; ++j2)
                #pragma unroll
                for (int q = 0; q < 4; ++q) {
                    int G = q * HID + cta * 4 + 2 * pr + j2;
                    xp[j2 * 4 + q] =
                        __ldg(&g_xproj[(size_t)G * NJ + (size_t)t * 32 + b]);
                }
        }

        // ---- stage h planes (pure copy, 64KB) ----
        #pragma unroll
        for (int i = 0; i < 8; ++i) {
            int lin = tid + i * 256;              // uint4 index, 0..2047
            int k2 = lin >> 3, b4 = (lin & 7) * 4;
            uint4 vh = __ldcg(reinterpret_cast<const uint4*>(&g_hhi[cur][lin * 4]));
            uint4 vl = __ldcg(reinterpret_cast<const uint4*>(&g_hlo[cur][lin * 4]));
            *reinterpret_cast<uint4*>(&s_hhi[k2 * HSW + b4]) = vh;
            *reinterpret_cast<uint4*>(&s_hlo[k2 * HSW + b4]) = vl;
        }
        __syncthreads();

        // ---- mma: warp w covers k2 in [w*32, w*32+32) ----
        float acc[4][4];
        #pragma unroll
        for (int n = 0; n < 4; ++n)
            #pragma unroll
            for (int r = 0; r < 4; ++r) acc[n][r] = 0.f;

        #pragma unroll
        for (int kt = 0; kt < 4; ++kt) {
            const int base = w * 32 + kt * 8;
            #pragma unroll
            for (int n = 0; n < 4; ++n) {
                int col = n * 8 + gq;
                unsigned bh0 = s_hhi[(base + tg) * HSW + col];
                unsigned bh1 = s_hhi[(base + tg + 4) * HSW + col];
                unsigned bl0 = s_hlo[(base + tg) * HSW + col];
                unsigned bl1 = s_hlo[(base + tg + 4) * HSW + col];
                mma_bf16(acc[n], Ahi[kt], bh0, bh1);
                mma_bf16(acc[n], Ahi[kt], bl0, bl1);
                mma_bf16(acc[n], Alo[kt], bh0, bh1);
            }
        }

        // ---- partials ----
        {
            float* p = part + w * (16 * 33);
            #pragma unroll
            for (int n = 0; n < 4; ++n) {
                int ci = n * 8 + 2 * tg;
                p[gq * 33 + ci]           = acc[n][0];
                p[gq * 33 + ci + 1]       = acc[n][1];
                p[(gq + 8) * 33 + ci]     = acc[n][2];
                p[(gq + 8) * 33 + ci + 1] = acc[n][3];
            }
        }
        __syncthreads();

        // ---- reduce + cell update (tid<64), write packed h ----
        if (tid < 64) {
            float hv[2];
            #pragma unroll
            for (int j2 = 0; j2 < 2; ++j2) {
                int uu = 2 * pr + j2;
                float gs[4];
                #pragma unroll
                for (int q = 0; q < 4; ++q) {
                    int r = uu * 4 + q;
                    float s = xp[j2 * 4 + q];
                    #pragma unroll
                    for (int ww = 0; ww < 8; ++ww)
                        s += part[ww * (16 * 33) + r * 33 + b];
                    gs[q] = s;
                }
                float i_ = sigf(gs[0]);
                float f_ = sigf(gs[1]);
                float g_ = tanh_fast(gs[2]);
                float o_ = sigf(gs[3]);
                float c = f_ * cst[j2] + i_ * g_;
                cst[j2] = c;
                hv[j2] = o_ * tanh_fast(c);
                if (t == T_SEQ - 1) {
                    int u = cta * 4 + uu;
                    out[b * HID + u] = hv[j2];
                    out[BATCH * HID + b * HID + u] = c;
                }
            }
            unsigned lo;
            unsigned hi = split_pack(hv[0], hv[1], lo);
            int widx = (cta * 2 + pr) * 32 + b;
            g_hhi[cur ^ 1][widx] = hi;
            g_hlo[cur ^ 1][widx] = lo;
            __threadfence();
        }

        // ---- grid barrier ----
        __syncthreads();
        if (tid == 0) {
            __threadfence();
            unsigned v = atomicAdd(&g_bar, 1u) + 1u;
            if (v < target) {
                while (atomicAdd(&g_bar, 0u) < target) { __nanosleep(32); }
            }
        }
        __syncthreads();
        target += NCTA;
    }
}

// =====================================================================
// launch
// =====================================================================
extern "C" void kernel_launch(void* const* d_in, const int* in_sizes, int n_in,
                              void* d_out, int out_size)
{
    const float* input = (const float*)d_in[0];
    const float* h0    = (const float*)d_in[1];
    const float* c0    = (const float*)d_in[2];
    const float* W_ih  = (const float*)d_in[3];
    const float* W_hh  = (const float*)d_in[4];
    const float* b_ih  = (const float*)d_in[5];
    const float* b_hh  = (const float*)d_in[6];
    float* out = (float*)d_out;

    cudaFuncSetAttribute(lstm_kernel,
                         cudaFuncAttributeMaxDynamicSharedMemorySize,
                         (int)SMEM_BYTES);

    convert_kernel<<<2048, 256>>>(input, W_ih);
    init_kernel<<<32, 256>>>(h0);
    xproj_kernel<<<dim3(16, 512), 256>>>(b_ih, b_hh);
    lstm_kernel<<<NCTA, 256, SMEM_BYTES>>>(W_hh, c0, out);
}

// round 6
// speedup vs baseline: 2.5364x; 1.0933x over previous
#include <cuda_runtime.h>
#include <cuda_bf16.h>
#include <cstdint>

#define T_SEQ 2048
#define BATCH 32
#define DIM   512
#define HID   512
#define G4    2048
#define NJ    (T_SEQ * BATCH)   // 65536
#define NCTA  128

// ---------------- static device scratch ----------------
__device__ float    g_xproj[(size_t)G4 * NJ];                  // [g][t*32+b] fp32 (512MB)
__device__ unsigned g_xhi[(size_t)BATCH * T_SEQ * DIM / 2];    // bf16 pairs along d
__device__ unsigned g_xlo[(size_t)BATCH * T_SEQ * DIM / 2];
__device__ unsigned g_whi[(size_t)G4 * DIM / 2];
__device__ unsigned g_wlo[(size_t)G4 * DIM / 2];
__device__ unsigned g_hhi[2][(HID / 2) * BATCH];               // word idx = k2*32+b
__device__ unsigned g_hlo[2][(HID / 2) * BATCH];
__device__ unsigned g_bar;

// ---------------- helpers ----------------
__device__ __forceinline__ void mma_bf16(float c[4], const unsigned a[4],
                                         unsigned b0, unsigned b1) {
    asm volatile(
        "mma.sync.aligned.m16n8k16.row.col.f32.bf16.bf16.f32 "
        "{%0,%1,%2,%3}, {%4,%5,%6,%7}, {%8,%9}, {%0,%1,%2,%3};\n"
        : "+f"(c[0]), "+f"(c[1]), "+f"(c[2]), "+f"(c[3])
        : "r"(a[0]), "r"(a[1]), "r"(a[2]), "r"(a[3]), "r"(b0), "r"(b1));
}

__device__ __forceinline__ unsigned split_pack(float v0, float v1, unsigned& lo_bits) {
    __nv_bfloat162 hi = __floats2bfloat162_rn(v0, v1);
    __nv_bfloat162 lo = __floats2bfloat162_rn(v0 - __bfloat162float(hi.x),
                                              v1 - __bfloat162float(hi.y));
    lo_bits = *reinterpret_cast<unsigned*>(&lo);
    return *reinterpret_cast<unsigned*>(&hi);
}

__device__ __forceinline__ float sigf(float x) {
    return __fdividef(1.f, 1.f + __expf(-x));
}
__device__ __forceinline__ float tanh_fast(float x) {
    return __fdividef(2.f, 1.f + __expf(-2.f * x)) - 1.f;
}

__device__ __forceinline__ void bar_arrive_release() {
    unsigned* p = &g_bar;
    asm volatile("red.release.gpu.global.add.u32 [%0], %1;" :: "l"(p), "r"(1u) : "memory");
}
__device__ __forceinline__ unsigned bar_load_acquire() {
    unsigned v;
    unsigned* p = &g_bar;
    asm volatile("ld.acquire.gpu.global.u32 %0, [%1];" : "=r"(v) : "l"(p) : "memory");
    return v;
}

// =====================================================================
// convert: split input & W_ih into bf16 hi/lo packed-pair planes
// =====================================================================
__global__ void convert_kernel(const float* __restrict__ x,
                               const float* __restrict__ wih)
{
    const size_t n_x = (size_t)BATCH * T_SEQ * DIM / 2;
    const size_t n_w = (size_t)G4 * DIM / 2;
    const size_t stride = (size_t)gridDim.x * blockDim.x;
    for (size_t i = blockIdx.x * (size_t)blockDim.x + threadIdx.x;
         i < n_x; i += stride) {
        float2 v = reinterpret_cast<const float2*>(x)[i];
        unsigned lo;
        unsigned hi = split_pack(v.x, v.y, lo);
        g_xhi[i] = hi; g_xlo[i] = lo;
    }
    for (size_t i = blockIdx.x * (size_t)blockDim.x + threadIdx.x;
         i < n_w; i += stride) {
        float2 v = reinterpret_cast<const float2*>(wih)[i];
        unsigned lo;
        unsigned hi = split_pack(v.x, v.y, lo);
        g_whi[i] = hi; g_wlo[i] = lo;
    }
}

// =====================================================================
// init: h planes (buffer 0) from h0, reset barrier
// =====================================================================
__global__ void init_kernel(const float* __restrict__ h0)
{
    int i = blockIdx.x * blockDim.x + threadIdx.x;
    if (i < (HID / 2) * BATCH) {
        int k2 = i >> 5, b = i & 31;
        float v0 = h0[b * HID + 2 * k2];
        float v1 = h0[b * HID + 2 * k2 + 1];
        unsigned lo;
        unsigned hi = split_pack(v0, v1, lo);
        g_hhi[0][i] = hi; g_hlo[0][i] = lo;
    }
    if (i == 0) g_bar = 0u;
}

// =====================================================================
// Phase 1: x_proj via bf16x3 mma, 2-stage pipelined (double-buffer smem,
// register prefetch of chunk c+1 during mma of chunk c, 1 sync/chunk).
// CTA tile 128(g) x 128(j), K-chunk 32.  grid=(16,512), 256 thr.
// =====================================================================
#define SA 20
#define XPLANE (128 * SA)              // words per plane
#define XBUF   (4 * XPLANE)            // words per buffer (Ah|Al|Bh|Bl)
#define XSMEM_WORDS (2 * XBUF)         // 20480 words = 80KB
#define XSMEM_BYTES (XSMEM_WORDS * 4)

__global__ __launch_bounds__(256) void xproj_kernel(
    const float* __restrict__ b_ih,
    const float* __restrict__ b_hh)
{
    extern __shared__ unsigned xsm[];

    const int tid = threadIdx.x;
    const int w = tid >> 5, lane = tid & 31;
    const int gq = lane >> 2, tg = lane & 3;
    const int gm0 = blockIdx.x * 128;
    const int jn0 = blockIdx.y * 128;
    const int wm = (w >> 2) * 64;
    const int wn = (w & 3) * 32;

    // per-thread staging coordinates (2 uint4 positions)
    int s_m[2], s_q4[2];
    size_t gwA[2], gwB[2];
    #pragma unroll
    for (int i = 0; i < 2; ++i) {
        int idx = tid + i * 256;
        int m = idx >> 2, q4 = (idx & 3) * 4;
        s_m[i] = m; s_q4[i] = q4;
        gwA[i] = (size_t)(gm0 + m) * (DIM / 2) + q4;
        int b = m & 31;
        int t = (jn0 + m) >> 5;
        gwB[i] = ((size_t)b * T_SEQ + t) * (DIM / 2) + q4;
    }

    float acc[4][4][4];
    #pragma unroll
    for (int m = 0; m < 4; ++m)
        #pragma unroll
        for (int n = 0; n < 4; ++n)
            #pragma unroll
            for (int r = 0; r < 4; ++r) acc[m][n][r] = 0.f;

    uint4 rAh[2], rAl[2], rBh[2], rBl[2];

    // prologue: load chunk 0
    #pragma unroll
    for (int i = 0; i < 2; ++i) {
        rAh[i] = *reinterpret_cast<const uint4*>(&g_whi[gwA[i]]);
        rAl[i] = *reinterpret_cast<const uint4*>(&g_wlo[gwA[i]]);
        rBh[i] = *reinterpret_cast<const uint4*>(&g_xhi[gwB[i]]);
        rBl[i] = *reinterpret_cast<const uint4*>(&g_xlo[gwB[i]]);
    }
    {
        unsigned* buf = xsm;
        #pragma unroll
        for (int i = 0; i < 2; ++i) {
            int off = s_m[i] * SA + s_q4[i];
            *reinterpret_cast<uint4*>(&buf[off])              = rAh[i];
            *reinterpret_cast<uint4*>(&buf[XPLANE + off])     = rAl[i];
            *reinterpret_cast<uint4*>(&buf[2 * XPLANE + off]) = rBh[i];
            *reinterpret_cast<uint4*>(&buf[3 * XPLANE + off]) = rBl[i];
        }
    }
    __syncthreads();

    int p = 0;
    for (int c = 0; c < 16; ++c) {
        // prefetch chunk c+1 into regs (in flight during mma)
        if (c + 1 < 16) {
            const size_t ko = (size_t)(c + 1) * 16;
            #pragma unroll
            for (int i = 0; i < 2; ++i) {
                rAh[i] = *reinterpret_cast<const uint4*>(&g_whi[gwA[i] + ko]);
                rAl[i] = *reinterpret_cast<const uint4*>(&g_wlo[gwA[i] + ko]);
                rBh[i] = *reinterpret_cast<const uint4*>(&g_xhi[gwB[i] + ko]);
                rBl[i] = *reinterpret_cast<const uint4*>(&g_xlo[gwB[i] + ko]);
            }
        }

        // mma on buffer p
        unsigned* Ahs = xsm + p * XBUF;
        unsigned* Als = Ahs + XPLANE;
        unsigned* Bhs = Ahs + 2 * XPLANE;
        unsigned* Bls = Ahs + 3 * XPLANE;

        #pragma unroll
        for (int kt = 0; kt < 2; ++kt) {
            const int k2o = kt * 8;
            unsigned bh[4][2], bl[4][2];
            #pragma unroll
            for (int n = 0; n < 4; ++n) {
                int j = wn + n * 8 + gq;
                bh[n][0] = Bhs[j * SA + k2o + tg];
                bh[n][1] = Bhs[j * SA + k2o + tg + 4];
                bl[n][0] = Bls[j * SA + k2o + tg];
                bl[n][1] = Bls[j * SA + k2o + tg + 4];
            }
            #pragma unroll
            for (int m = 0; m < 4; ++m) {
                int r0 = wm + m * 16 + gq;
                unsigned ah[4], al[4];
                ah[0] = Ahs[r0 * SA + k2o + tg];
                ah[1] = Ahs[(r0 + 8) * SA + k2o + tg];
                ah[2] = Ahs[r0 * SA + k2o + tg + 4];
                ah[3] = Ahs[(r0 + 8) * SA + k2o + tg + 4];
                al[0] = Als[r0 * SA + k2o + tg];
                al[1] = Als[(r0 + 8) * SA + k2o + tg];
                al[2] = Als[r0 * SA + k2o + tg + 4];
                al[3] = Als[(r0 + 8) * SA + k2o + tg + 4];
                #pragma unroll
                for (int n = 0; n < 4; ++n) {
                    mma_bf16(acc[m][n], ah, bh[n][0], bh[n][1]);
                    mma_bf16(acc[m][n], ah, bl[n][0], bl[n][1]);
                    mma_bf16(acc[m][n], al, bh[n][0], bh[n][1]);
                }
            }
        }

        // store prefetched chunk into other buffer, one sync
        if (c + 1 < 16) {
            unsigned* buf = xsm + (p ^ 1) * XBUF;
            #pragma unroll
            for (int i = 0; i < 2; ++i) {
                int off = s_m[i] * SA + s_q4[i];
                *reinterpret_cast<uint4*>(&buf[off])              = rAh[i];
                *reinterpret_cast<uint4*>(&buf[XPLANE + off])     = rAl[i];
                *reinterpret_cast<uint4*>(&buf[2 * XPLANE + off]) = rBh[i];
                *reinterpret_cast<uint4*>(&buf[3 * XPLANE + off]) = rBl[i];
            }
            __syncthreads();
            p ^= 1;
        }
    }

    // ---- epilogue: bias + fp32 store ----
    #pragma unroll
    for (int m = 0; m < 4; ++m) {
        int g0 = gm0 + wm + m * 16 + gq;
        float bi0 = __ldg(b_ih + g0) + __ldg(b_hh + g0);
        float bi1 = __ldg(b_ih + g0 + 8) + __ldg(b_hh + g0 + 8);
        #pragma unroll
        for (int n = 0; n < 4; ++n) {
            int j0 = jn0 + wn + n * 8 + tg * 2;
            float2 v0 = make_float2(acc[m][n][0] + bi0, acc[m][n][1] + bi0);
            float2 v1 = make_float2(acc[m][n][2] + bi1, acc[m][n][3] + bi1);
            *reinterpret_cast<float2*>(g_xproj + (size_t)g0 * NJ + j0) = v0;
            *reinterpret_cast<float2*>(g_xproj + (size_t)(g0 + 8) * NJ + j0) = v1;
        }
    }
}

// =====================================================================
// Phase 2: persistent recurrent kernel, bf16x3, per-warp self-staging.
//   Warp w stages + consumes k2 in [w*32,(w+1)*32) -> no pre-mma sync.
//   Barrier: red.release arrive + ld.acquire poll (no fences).
// =====================================================================
#define HSW 40
#define SMEM_WORDS (2 * 256 * HSW + 8 * 16 * 33)
#define SMEM_BYTES (SMEM_WORDS * 4)

__global__ __launch_bounds__(256) void lstm_kernel(
    const float* __restrict__ W_hh,
    const float* __restrict__ c0,
    float* __restrict__ out)
{
    extern __shared__ unsigned smw[];
    unsigned* s_hhi = smw;                    // [256 k2][HSW]
    unsigned* s_hlo = smw + 256 * HSW;
    float*    part  = reinterpret_cast<float*>(smw + 2 * 256 * HSW); // [8][16][33]

    const int tid = threadIdx.x;
    const int cta = blockIdx.x;
    const int w = tid >> 5, lane = tid & 31;
    const int gq = lane >> 2, tg = lane & 3;

    // ---- W_hh frags into registers (hi/lo), once ----
    unsigned Ahi[4][4], Alo[4][4];
    #pragma unroll
    for (int kt = 0; kt < 4; ++kt) {
        #pragma unroll
        for (int i = 0; i < 4; ++i) {
            int r   = gq + ((i & 1) << 3);
            int k2l = tg + ((i >> 1) << 2);
            int kg  = w * 64 + kt * 16 + k2l * 2;
            int G   = (r & 3) * HID + cta * 4 + (r >> 2);
            float w0 = __ldg(W_hh + (size_t)G * HID + kg);
            float w1 = __ldg(W_hh + (size_t)G * HID + kg + 1);
            unsigned lo;
            Ahi[kt][i] = split_pack(w0, w1, lo);
            Alo[kt][i] = lo;
        }
    }

    // cell threads: tid<64, pair pr = tid>>5 (units 2pr,2pr+1), batch b
    const int pr = tid >> 5;
    const int b  = lane;
    float cst[2] = {0.f, 0.f};
    if (tid < 64) {
        cst[0] = __ldg(c0 + b * HID + cta * 4 + 2 * pr);
        cst[1] = __ldg(c0 + b * HID + cta * 4 + 2 * pr + 1);
    }

    unsigned target = NCTA;

    for (int t = 0; t < T_SEQ; ++t) {
        const int cur = t & 1;

        // ---- xp prefetch (cell threads) ----
        float xp[8];
        if (tid < 64) {
            #pragma unroll
            for (int j2 = 0; j2 < 2; ++j2)
                #pragma unroll
                for (int q = 0; q < 4; ++q) {
                    int G = q * HID + cta * 4 + 2 * pr + j2;
                    xp[j2 * 4 + q] =
                        __ldg(&g_xproj[(size_t)G * NJ + (size_t)t * 32 + b]);
                }
        }

        // ---- per-warp self-staging: warp w stages its own 32 k2 rows ----
        #pragma unroll
        for (int i = 0; i < 8; ++i) {
            int lin = w * 256 + i * 32 + lane;     // uint4 idx within plane
            int k2 = lin >> 3, b4 = (lin & 7) * 4;
            uint4 vh = __ldcg(reinterpret_cast<const uint4*>(&g_hhi[cur][lin * 4]));
            uint4 vl = __ldcg(reinterpret_cast<const uint4*>(&g_hlo[cur][lin * 4]));
            *reinterpret_cast<uint4*>(&s_hhi[k2 * HSW + b4]) = vh;
            *reinterpret_cast<uint4*>(&s_hlo[k2 * HSW + b4]) = vl;
        }
        // no syncthreads: warp consumes only its own staged slice

        // ---- mma: warp w covers k2 in [w*32, w*32+32) ----
        float acc[4][4];
        #pragma unroll
        for (int n = 0; n < 4; ++n)
            #pragma unroll
            for (int r = 0; r < 4; ++r) acc[n][r] = 0.f;

        #pragma unroll
        for (int kt = 0; kt < 4; ++kt) {
            const int base = w * 32 + kt * 8;
            #pragma unroll
            for (int n = 0; n < 4; ++n) {
                int col = n * 8 + gq;
                unsigned bh0 = s_hhi[(base + tg) * HSW + col];
                unsigned bh1 = s_hhi[(base + tg + 4) * HSW + col];
                unsigned bl0 = s_hlo[(base + tg) * HSW + col];
                unsigned bl1 = s_hlo[(base + tg + 4) * HSW + col];
                mma_bf16(acc[n], Ahi[kt], bh0, bh1);
                mma_bf16(acc[n], Ahi[kt], bl0, bl1);
                mma_bf16(acc[n], Alo[kt], bh0, bh1);
            }
        }

        // ---- partials ----
        {
            float* p = part + w * (16 * 33);
            #pragma unroll
            for (int n = 0; n < 4; ++n) {
                int ci = n * 8 + 2 * tg;
                p[gq * 33 + ci]           = acc[n][0];
                p[gq * 33 + ci + 1]       = acc[n][1];
                p[(gq + 8) * 33 + ci]     = acc[n][2];
                p[(gq + 8) * 33 + ci + 1] = acc[n][3];
            }
        }
        __syncthreads();

        // ---- reduce + cell update (tid<64), write packed h ----
        if (tid < 64) {
            float hv[2];
            #pragma unroll
            for (int j2 = 0; j2 < 2; ++j2) {
                int uu = 2 * pr + j2;
                float gs[4];
                #pragma unroll
                for (int q = 0; q < 4; ++q) {
                    int r = uu * 4 + q;
                    float s = xp[j2 * 4 + q];
                    #pragma unroll
                    for (int ww = 0; ww < 8; ++ww)
                        s += part[ww * (16 * 33) + r * 33 + b];
                    gs[q] = s;
                }
                float i_ = sigf(gs[0]);
                float f_ = sigf(gs[1]);
                float g_ = tanh_fast(gs[2]);
                float o_ = sigf(gs[3]);
                float c = f_ * cst[j2] + i_ * g_;
                cst[j2] = c;
                hv[j2] = o_ * tanh_fast(c);
                if (t == T_SEQ - 1) {
                    int u = cta * 4 + uu;
                    out[b * HID + u] = hv[j2];
                    out[BATCH * HID + b * HID + u] = c;
                }
            }
            unsigned lo;
            unsigned hi = split_pack(hv[0], hv[1], lo);
            int widx = (cta * 2 + pr) * 32 + b;
            g_hhi[cur ^ 1][widx] = hi;
            g_hlo[cur ^ 1][widx] = lo;
        }

        // ---- grid barrier: release arrive, acquire poll ----
        __syncthreads();
        if (tid == 0) {
            bar_arrive_release();
            while (bar_load_acquire() < target) { }
        }
        __syncthreads();
        target += NCTA;
    }
}

// =====================================================================
// launch
// =====================================================================
extern "C" void kernel_launch(void* const* d_in, const int* in_sizes, int n_in,
                              void* d_out, int out_size)
{
    const float* input = (const float*)d_in[0];
    const float* h0    = (const float*)d_in[1];
    const float* c0    = (const float*)d_in[2];
    const float* W_ih  = (const float*)d_in[3];
    const float* W_hh  = (const float*)d_in[4];
    const float* b_ih  = (const float*)d_in[5];
    const float* b_hh  = (const float*)d_in[6];
    float* out = (float*)d_out;

    cudaFuncSetAttribute(lstm_kernel,
                         cudaFuncAttributeMaxDynamicSharedMemorySize,
                         (int)SMEM_BYTES);
    cudaFuncSetAttribute(xproj_kernel,
                         cudaFuncAttributeMaxDynamicSharedMemorySize,
                         (int)XSMEM_BYTES);

    convert_kernel<<<2048, 256>>>(input, W_ih);
    init_kernel<<<32, 256>>>(h0);
    xproj_kernel<<<dim3(16, 512), 256, XSMEM_BYTES>>>(b_ih, b_hh);
    lstm_kernel<<<NCTA, 256, SMEM_BYTES>>>(W_hh, c0, out);
}